// round 2
// baseline (speedup 1.0000x reference)
#include <cuda_runtime.h>
#include <cuda_bf16.h>

// Problem shapes (fixed by the dataset)
#define BB   16384
#define CC   10
#define KK   8
#define DIM  128

// Scratch: per-example loss (device global => allowed; no cudaMalloc anywhere)
__device__ float g_row[BB];

// Stage 1: one block per example, 128 threads = one thread per embedding dim.
//  - gather+sum 10 context rows  -> src[d]   (per-thread scalar)
//  - gather 8 target rows, per-dim product, block-reduce to pred[k]
//  - stable softplus BCE, weighted, row-renormalized -> g_row[b]
__global__ void __launch_bounds__(128) cbow_main(
    const int*   __restrict__ contexts,   // [B, C]
    const int*   __restrict__ focus,      // [B, K]
    const float* __restrict__ wmask,      // [B, K]
    const float* __restrict__ labels,     // [B, K]
    const float* __restrict__ ctx_emb,    // [VOCAB, DIM]
    const float* __restrict__ neg_emb)    // [VOCAB, DIM]
{
    const int b    = blockIdx.x;
    const int tid  = threadIdx.x;     // = dim index d
    const int lane = tid & 31;
    const int warp = tid >> 5;

    __shared__ int   s_ctx[CC];
    __shared__ int   s_foc[KK];
    __shared__ float s_w[KK];
    __shared__ float s_y[KK];
    __shared__ float s_part[KK][4];   // per-warp partial dots
    __shared__ float s_bce[KK];

    if (tid < CC) s_ctx[tid] = contexts[b * CC + tid];
    if (tid < KK) {
        s_foc[tid] = focus[b * KK + tid];
        s_w[tid]   = wmask[b * KK + tid];
        s_y[tid]   = labels[b * KK + tid];
    }
    __syncthreads();

    // Sum-pooled context embedding, one scalar per thread.
    // 10 independent LDGs -> MLP ~10, each warp reads a contiguous 128B line.
    float src = 0.0f;
#pragma unroll
    for (int c = 0; c < CC; ++c)
        src += __ldg(&ctx_emb[(size_t)s_ctx[c] * DIM + tid]);

    // Per-dim products with each of the K target rows (8 more independent LDGs)
    float p[KK];
#pragma unroll
    for (int k = 0; k < KK; ++k)
        p[k] = src * __ldg(&neg_emb[(size_t)s_foc[k] * DIM + tid]);

    // Reduce each p[k] across the 128 threads: warp shuffles, then smem
#pragma unroll
    for (int k = 0; k < KK; ++k) {
        float v = p[k];
        v += __shfl_xor_sync(0xffffffffu, v, 16);
        v += __shfl_xor_sync(0xffffffffu, v, 8);
        v += __shfl_xor_sync(0xffffffffu, v, 4);
        v += __shfl_xor_sync(0xffffffffu, v, 2);
        v += __shfl_xor_sync(0xffffffffu, v, 1);
        if (lane == 0) s_part[k][warp] = v;
    }
    __syncthreads();

    if (tid < KK) {
        float pred = s_part[tid][0] + s_part[tid][1]
                   + s_part[tid][2] + s_part[tid][3];
        // logaddexp(0, x) = max(x,0) + log1p(exp(-|x|))  (stable softplus)
        float sp = fmaxf(pred, 0.0f) + log1pf(expf(-fabsf(pred)));
        s_bce[tid] = s_w[tid] * (sp - pred * s_y[tid]);
    }
    __syncthreads();

    if (tid == 0) {
        float num = 0.0f, den = 0.0f;
#pragma unroll
        for (int k = 0; k < KK; ++k) { num += s_bce[k]; den += s_w[k]; }
        // mean over K * K / sum(w)  ==  sum(bce) / sum(w)
        g_row[b] = num / den;
    }
}

// Stage 2: deterministic single-block reduction of g_row -> scalar mean.
// 1024 threads (32 warps) => 16 L2-resident loads per thread, latency hidden.
__global__ void __launch_bounds__(1024) cbow_reduce(float* __restrict__ out)
{
    __shared__ double s_acc[32];
    const int tid  = threadIdx.x;
    const int lane = tid & 31;
    const int warp = tid >> 5;

    double acc = 0.0;
#pragma unroll
    for (int i = tid; i < BB; i += 1024)
        acc += (double)g_row[i];

#pragma unroll
    for (int o = 16; o > 0; o >>= 1)
        acc += __shfl_xor_sync(0xffffffffu, acc, o);
    if (lane == 0) s_acc[warp] = acc;
    __syncthreads();

    if (tid < 32) {
        double v = s_acc[tid];
#pragma unroll
        for (int o = 16; o > 0; o >>= 1)
            v += __shfl_xor_sync(0xffffffffu, v, o);
        if (tid == 0) out[0] = (float)(v / (double)BB);
    }
}

extern "C" void kernel_launch(void* const* d_in, const int* in_sizes, int n_in,
                              void* d_out, int out_size)
{
    const int*   contexts = (const int*)  d_in[0];   // [B, C] int32
    const int*   focus    = (const int*)  d_in[1];   // [B, K] int32
    const float* wmask    = (const float*)d_in[2];   // [B, K] f32
    const float* labels   = (const float*)d_in[3];   // [B, K] f32
    const float* ctx_emb  = (const float*)d_in[4];   // [VOCAB, DIM] f32
    const float* neg_emb  = (const float*)d_in[5];   // [VOCAB, DIM] f32
    float* out = (float*)d_out;

    cbow_main<<<BB, 128>>>(contexts, focus, wmask, labels, ctx_emb, neg_emb);
    cbow_reduce<<<1, 1024>>>(out);
}

// round 3
// speedup vs baseline: 1.9276x; 1.9276x over previous
#include <cuda_runtime.h>
#include <cuda_bf16.h>

// Problem shapes (fixed by the dataset)
#define BB   16384
#define CC   10
#define KK   8
#define DIM  128

#define WARPS_PER_BLOCK 8
#define NPART 128

// Scratch (device globals: allocation-guard-safe)
__device__ float  g_row[BB];
__device__ double g_part[NPART];

// Stage 1: one WARP per example. Lane l holds dims [4l..4l+3] as float4.
// Warp-autonomous: index broadcast + dot reductions via shuffles only.
__global__ void __launch_bounds__(32 * WARPS_PER_BLOCK) cbow_main(
    const int*   __restrict__ contexts,   // [B, C]
    const int*   __restrict__ focus,      // [B, K]
    const float* __restrict__ wmask,      // [B, K]
    const float* __restrict__ labels,     // [B, K]
    const float* __restrict__ ctx_emb,    // [VOCAB, DIM]
    const float* __restrict__ neg_emb)    // [VOCAB, DIM]
{
    const int lane = threadIdx.x & 31;
    const int b    = blockIdx.x * WARPS_PER_BLOCK + (threadIdx.x >> 5);

    // Per-lane index/label staging (lanes < C / < K own one entry each)
    int   ctx_i = (lane < CC) ? contexts[b * CC + lane] : 0;
    int   foc_i = (lane < KK) ? focus[b * KK + lane]    : 0;
    float w     = (lane < KK) ? wmask [b * KK + lane]   : 0.0f;
    float y     = (lane < KK) ? labels[b * KK + lane]   : 0.0f;

    // Sum-pooled context embedding: 10 independent LDG.128 per lane
    float4 src = make_float4(0.f, 0.f, 0.f, 0.f);
#pragma unroll
    for (int c = 0; c < CC; ++c) {
        int row = __shfl_sync(0xffffffffu, ctx_i, c);
        float4 v = __ldg((const float4*)&ctx_emb[(size_t)row * DIM + lane * 4]);
        src.x += v.x; src.y += v.y; src.z += v.z; src.w += v.w;
    }

    // K dot products; butterfly so all lanes see the sum, lane k keeps pred_k
    float pred_mine = 0.0f;
#pragma unroll
    for (int k = 0; k < KK; ++k) {
        int row = __shfl_sync(0xffffffffu, foc_i, k);
        float4 t = __ldg((const float4*)&neg_emb[(size_t)row * DIM + lane * 4]);
        float d = src.x * t.x + src.y * t.y + src.z * t.z + src.w * t.w;
        d += __shfl_xor_sync(0xffffffffu, d, 16);
        d += __shfl_xor_sync(0xffffffffu, d, 8);
        d += __shfl_xor_sync(0xffffffffu, d, 4);
        d += __shfl_xor_sync(0xffffffffu, d, 2);
        d += __shfl_xor_sync(0xffffffffu, d, 1);
        if (lane == k) pred_mine = d;
    }

    // Lane k (k < K) computes its weighted BCE term once
    float bce = 0.0f;
    if (lane < KK) {
        // logaddexp(0, x) = max(x,0) + log1p(exp(-|x|))  (stable softplus)
        float sp = fmaxf(pred_mine, 0.0f) + log1pf(expf(-fabsf(pred_mine)));
        bce = w * (sp - pred_mine * y);
    }

    // num = sum_k bce, den = sum_k w  (w is 0 on lanes >= K)
    float num = bce, den = w;
#pragma unroll
    for (int o = 16; o > 0; o >>= 1) {
        num += __shfl_xor_sync(0xffffffffu, num, o);
        den += __shfl_xor_sync(0xffffffffu, den, o);
    }

    if (lane == 0) g_row[b] = num / den;   // mean_K * K / sum(w) == sum/sum(w)
}

// Stage 2a: 128 blocks x 128 threads, each block reduces 128 row losses
__global__ void __launch_bounds__(128) cbow_reduce1()
{
    __shared__ float s_acc[4];
    const int tid  = threadIdx.x;
    const int lane = tid & 31;
    const int warp = tid >> 5;

    float v = g_row[blockIdx.x * 128 + tid];
#pragma unroll
    for (int o = 16; o > 0; o >>= 1)
        v += __shfl_xor_sync(0xffffffffu, v, o);
    if (lane == 0) s_acc[warp] = v;
    __syncthreads();

    if (tid == 0)
        g_part[blockIdx.x] = (double)(s_acc[0] + s_acc[1] + s_acc[2] + s_acc[3]);
}

// Stage 2b: single small block finishes 128 partials -> scalar mean
__global__ void __launch_bounds__(128) cbow_reduce2(float* __restrict__ out)
{
    __shared__ double s_acc[4];
    const int tid  = threadIdx.x;
    const int lane = tid & 31;
    const int warp = tid >> 5;

    double v = g_part[tid];
#pragma unroll
    for (int o = 16; o > 0; o >>= 1)
        v += __shfl_xor_sync(0xffffffffu, v, o);
    if (lane == 0) s_acc[warp] = v;
    __syncthreads();

    if (tid == 0)
        out[0] = (float)((s_acc[0] + s_acc[1] + s_acc[2] + s_acc[3]) / (double)BB);
}

extern "C" void kernel_launch(void* const* d_in, const int* in_sizes, int n_in,
                              void* d_out, int out_size)
{
    const int*   contexts = (const int*)  d_in[0];   // [B, C] int32
    const int*   focus    = (const int*)  d_in[1];   // [B, K] int32
    const float* wmask    = (const float*)d_in[2];   // [B, K] f32
    const float* labels   = (const float*)d_in[3];   // [B, K] f32
    const float* ctx_emb  = (const float*)d_in[4];   // [VOCAB, DIM] f32
    const float* neg_emb  = (const float*)d_in[5];   // [VOCAB, DIM] f32
    float* out = (float*)d_out;

    cbow_main<<<BB / WARPS_PER_BLOCK, 32 * WARPS_PER_BLOCK>>>(
        contexts, focus, wmask, labels, ctx_emb, neg_emb);
    cbow_reduce1<<<NPART, 128>>>();
    cbow_reduce2<<<1, 128>>>(out);
}